// round 1
// baseline (speedup 1.0000x reference)
#include <cuda_runtime.h>

// ChamferDistance: B=4, N=8192, C=3
// loss = sum_b [ mean_i min_j d2(p1[b,i], p2[b,j]) + mean_j min_i d2(...) ]

constexpr int B_     = 4;
constexpr int N_     = 8192;
constexpr int THREADS = 256;
constexpr int QPT    = 2;               // queries per thread
constexpr int QPB    = THREADS * QPT;   // 512 queries per block
constexpr int NBLK   = N_ / QPB;        // 16 blocks per (batch, direction)
constexpr int TILE   = 1024;            // reference points cached per smem tile
constexpr int NPART  = 2 * B_ * NBLK;   // 128 partial sums

__device__ float g_partial[NPART];

__global__ __launch_bounds__(THREADS)
void chamfer_min_kernel(const float* __restrict__ p1, const float* __restrict__ p2)
{
    const int dir = blockIdx.z;
    const int b   = blockIdx.y;
    const float* __restrict__ q = (dir == 0 ? p1 : p2) + (size_t)b * N_ * 3;
    const float* __restrict__ r = (dir == 0 ? p2 : p1) + (size_t)b * N_ * 3;

    __shared__ float4 sh[TILE];

    const int tid = threadIdx.x;
    const int i0  = blockIdx.x * QPB + tid;
    const int i1  = i0 + THREADS;

    // Load the two query points for this thread
    const float qx0 = q[i0 * 3 + 0], qy0 = q[i0 * 3 + 1], qz0 = q[i0 * 3 + 2];
    const float qx1 = q[i1 * 3 + 0], qy1 = q[i1 * 3 + 1], qz1 = q[i1 * 3 + 2];
    const float qs0 = qx0 * qx0 + qy0 * qy0 + qz0 * qz0;
    const float qs1 = qx1 * qx1 + qy1 * qy1 + qz1 * qz1;

    // Two independent running-min accumulators per query to relax the fmin chain
    float m0a = 1e30f, m0b = 1e30f;
    float m1a = 1e30f, m1b = 1e30f;

    for (int t = 0; t < N_; t += TILE) {
        __syncthreads();
        for (int i = tid; i < TILE; i += THREADS) {
            const float* rp = r + (size_t)(t + i) * 3;
            const float x = rp[0], y = rp[1], z = rp[2];
            sh[i] = make_float4(x, y, z, x * x + y * y + z * z);
        }
        __syncthreads();

        #pragma unroll 8
        for (int j = 0; j < TILE; j += 2) {
            {
                const float4 p = sh[j];
                float dot0 = qx0 * p.x;
                dot0 = fmaf(qy0, p.y, dot0);
                dot0 = fmaf(qz0, p.z, dot0);
                const float d0 = fmaf(-2.0f, dot0, p.w); // = |p|^2 - 2 q.p  (min-equivalent)
                m0a = fminf(m0a, d0);

                float dot1 = qx1 * p.x;
                dot1 = fmaf(qy1, p.y, dot1);
                dot1 = fmaf(qz1, p.z, dot1);
                const float d1 = fmaf(-2.0f, dot1, p.w);
                m1a = fminf(m1a, d1);
            }
            {
                const float4 p = sh[j + 1];
                float dot0 = qx0 * p.x;
                dot0 = fmaf(qy0, p.y, dot0);
                dot0 = fmaf(qz0, p.z, dot0);
                const float d0 = fmaf(-2.0f, dot0, p.w);
                m0b = fminf(m0b, d0);

                float dot1 = qx1 * p.x;
                dot1 = fmaf(qy1, p.y, dot1);
                dot1 = fmaf(qz1, p.z, dot1);
                const float d1 = fmaf(-2.0f, dot1, p.w);
                m1b = fminf(m1b, d1);
            }
        }
    }

    // Reconstruct true squared distances: d = q^2 + min(|p|^2 - 2 q.p), clamp >= 0
    float s = fmaxf(fminf(m0a, m0b) + qs0, 0.0f)
            + fmaxf(fminf(m1a, m1b) + qs1, 0.0f);

    // Deterministic block-sum reduction
    #pragma unroll
    for (int o = 16; o > 0; o >>= 1)
        s += __shfl_down_sync(0xffffffffu, s, o);

    __shared__ float red[THREADS / 32];
    if ((tid & 31) == 0) red[tid >> 5] = s;
    __syncthreads();
    if (tid < THREADS / 32) {
        s = red[tid];
        #pragma unroll
        for (int o = (THREADS / 32) / 2; o > 0; o >>= 1)
            s += __shfl_down_sync(0xffu, s, o);
        if (tid == 0)
            g_partial[(dir * B_ + b) * NBLK + blockIdx.x] = s;
    }
}

__global__ __launch_bounds__(NPART)
void chamfer_reduce_kernel(float* __restrict__ out)
{
    const int tid = threadIdx.x;
    float s = g_partial[tid];  // NPART == 128 threads, one partial each

    #pragma unroll
    for (int o = 16; o > 0; o >>= 1)
        s += __shfl_down_sync(0xffffffffu, s, o);

    __shared__ float red[NPART / 32];
    if ((tid & 31) == 0) red[tid >> 5] = s;
    __syncthreads();
    if (tid == 0) {
        float t = 0.0f;
        #pragma unroll
        for (int w = 0; w < NPART / 32; w++) t += red[w];
        out[0] = t * (1.0f / (float)N_);
    }
}

extern "C" void kernel_launch(void* const* d_in, const int* in_sizes, int n_in,
                              void* d_out, int out_size)
{
    const float* points1 = (const float*)d_in[0];
    const float* points2 = (const float*)d_in[1];
    float* out = (float*)d_out;

    dim3 grid(NBLK, B_, 2);
    chamfer_min_kernel<<<grid, THREADS>>>(points1, points2);
    chamfer_reduce_kernel<<<1, NPART>>>(out);
}

// round 3
// speedup vs baseline: 1.2575x; 1.2575x over previous
#include <cuda_runtime.h>
#include <cstdint>

// ChamferDistance: B=4, N=8192, C=3
// loss = sum_b [ mean_i min_j d2(p1[b,i], p2[b,j]) + mean_j min_i d2(...) ]
//
// d_j = |p_j|^2 - 2 q.p_j  (q^2 added after the min; -2 folded into query):
//   d = fma(nqz, pz, fma(nqy, py, fma(nqx, px, pw)))
// computed 2 reference points at a time with packed fma.rn.f32x2:
// 3 packed-FFMA issue slots per 2 distance columns on the fma pipe.
// Running min: scalar FMNMX on the alu pipe (parallel, non-binding).

constexpr int B_      = 4;
constexpr int N_      = 8192;
constexpr int THREADS = 256;
constexpr int QPT     = 2;               // queries per thread
constexpr int QPB     = THREADS * QPT;   // 512 queries per block
constexpr int NBLK    = N_ / QPB;        // 16 blocks per (batch, direction)
constexpr int TILE    = 1024;            // reference points cached per smem tile
constexpr int NPART   = 2 * B_ * NBLK;   // 128 partial sums
constexpr int NBLOCKS = NPART;           // one partial per block

__device__ float        g_partial[NPART];
__device__ unsigned int g_done = 0;

__device__ __forceinline__ uint64_t pack2(float lo, float hi) {
    uint64_t r;
    asm("mov.b64 %0, {%1, %2};" : "=l"(r) : "f"(lo), "f"(hi));
    return r;
}
__device__ __forceinline__ void unpack2(uint64_t v, float& lo, float& hi) {
    asm("mov.b64 {%0, %1}, %2;" : "=f"(lo), "=f"(hi) : "l"(v));
}
__device__ __forceinline__ uint64_t fma2(uint64_t a, uint64_t b, uint64_t c) {
    uint64_t r;
    asm("fma.rn.f32x2 %0, %1, %2, %3;" : "=l"(r) : "l"(a), "l"(b), "l"(c));
    return r;
}

__global__ __launch_bounds__(THREADS)
void chamfer_kernel(const float* __restrict__ p1, const float* __restrict__ p2,
                    float* __restrict__ out)
{
    const int dir = blockIdx.z;
    const int b   = blockIdx.y;
    const float* __restrict__ q = (dir == 0 ? p1 : p2) + (size_t)b * N_ * 3;
    const float* __restrict__ r = (dir == 0 ? p2 : p1) + (size_t)b * N_ * 3;

    // SoA smem: one 64-bit broadcast LDS per component yields a packed ref pair
    __shared__ float shx[TILE], shy[TILE], shz[TILE], shw[TILE];

    const int tid = threadIdx.x;
    const int i0  = blockIdx.x * QPB + tid;
    const int i1  = i0 + THREADS;

    const float qx0 = q[i0 * 3 + 0], qy0 = q[i0 * 3 + 1], qz0 = q[i0 * 3 + 2];
    const float qx1 = q[i1 * 3 + 0], qy1 = q[i1 * 3 + 1], qz1 = q[i1 * 3 + 2];
    const float qs0 = qx0 * qx0 + qy0 * qy0 + qz0 * qz0;
    const float qs1 = qx1 * qx1 + qy1 * qy1 + qz1 * qz1;

    // -2*q replicated into both packed halves (loop-invariant)
    const uint64_t nqx0 = pack2(-2.0f * qx0, -2.0f * qx0);
    const uint64_t nqy0 = pack2(-2.0f * qy0, -2.0f * qy0);
    const uint64_t nqz0 = pack2(-2.0f * qz0, -2.0f * qz0);
    const uint64_t nqx1 = pack2(-2.0f * qx1, -2.0f * qx1);
    const uint64_t nqy1 = pack2(-2.0f * qy1, -2.0f * qy1);
    const uint64_t nqz1 = pack2(-2.0f * qz1, -2.0f * qz1);

    // Two scalar min accumulators per query (lo/hi packed halves)
    float m0a = 1e30f, m0b = 1e30f;
    float m1a = 1e30f, m1b = 1e30f;

    const uint64_t* __restrict__ pxp = (const uint64_t*)shx;
    const uint64_t* __restrict__ pyp = (const uint64_t*)shy;
    const uint64_t* __restrict__ pzp = (const uint64_t*)shz;
    const uint64_t* __restrict__ pwp = (const uint64_t*)shw;

    for (int t = 0; t < N_; t += TILE) {
        __syncthreads();
        for (int i = tid; i < TILE; i += THREADS) {
            const float* rp = r + (size_t)(t + i) * 3;
            const float x = rp[0], y = rp[1], z = rp[2];
            shx[i] = x; shy[i] = y; shz[i] = z;
            shw[i] = x * x + y * y + z * z;
        }
        __syncthreads();

        #pragma unroll 8
        for (int j = 0; j < TILE / 2; j++) {
            const uint64_t px = pxp[j];   // (x_{2j}, x_{2j+1}) broadcast LDS.64
            const uint64_t py = pyp[j];
            const uint64_t pz = pzp[j];
            const uint64_t pw = pwp[j];

            // query 0: d = pw + nqx*px + nqy*py + nqz*pz (packed over 2 refs)
            uint64_t d0 = fma2(nqx0, px, pw);
            d0 = fma2(nqy0, py, d0);
            d0 = fma2(nqz0, pz, d0);
            float d0l, d0h; unpack2(d0, d0l, d0h);
            m0a = fminf(m0a, d0l);
            m0b = fminf(m0b, d0h);

            // query 1
            uint64_t d1 = fma2(nqx1, px, pw);
            d1 = fma2(nqy1, py, d1);
            d1 = fma2(nqz1, pz, d1);
            float d1l, d1h; unpack2(d1, d1l, d1h);
            m1a = fminf(m1a, d1l);
            m1b = fminf(m1b, d1h);
        }
    }

    // True squared distances: d = q^2 + min(|p|^2 - 2 q.p), clamped at 0
    float s = fmaxf(fminf(m0a, m0b) + qs0, 0.0f)
            + fmaxf(fminf(m1a, m1b) + qs1, 0.0f);

    // Deterministic block-sum reduction
    #pragma unroll
    for (int o = 16; o > 0; o >>= 1)
        s += __shfl_down_sync(0xffffffffu, s, o);

    __shared__ float red[THREADS / 32];
    __shared__ bool  amLast;
    if ((tid & 31) == 0) red[tid >> 5] = s;
    __syncthreads();
    if (tid == 0) {
        float bs = 0.0f;
        #pragma unroll
        for (int w = 0; w < THREADS / 32; w++) bs += red[w];
        g_partial[(dir * B_ + b) * NBLK + blockIdx.x] = bs;
        __threadfence();
        unsigned int prev = atomicAdd(&g_done, 1u);
        amLast = (prev == NBLOCKS - 1);
    }
    __syncthreads();

    // Last block to finish does the fixed-order final reduction
    if (amLast) {
        if (tid < NPART) {
            float v = g_partial[tid];
            #pragma unroll
            for (int o = 16; o > 0; o >>= 1)
                v += __shfl_down_sync(0xffffffffu, v, o);
            if ((tid & 31) == 0) red[tid >> 5] = v;
        }
        __syncthreads();
        if (tid == 0) {
            float tsum = 0.0f;
            #pragma unroll
            for (int w = 0; w < NPART / 32; w++) tsum += red[w];
            out[0] = tsum * (1.0f / (float)N_);
            g_done = 0;  // reset for next graph replay
        }
    }
}

extern "C" void kernel_launch(void* const* d_in, const int* in_sizes, int n_in,
                              void* d_out, int out_size)
{
    const float* points1 = (const float*)d_in[0];
    const float* points2 = (const float*)d_in[1];
    float* out = (float*)d_out;

    dim3 grid(NBLK, B_, 2);
    chamfer_kernel<<<grid, THREADS>>>(points1, points2, out);
}

// round 4
// speedup vs baseline: 1.3184x; 1.0484x over previous
#include <cuda_runtime.h>
#include <cstdint>

// ChamferDistance: B=4, N=8192, C=3
// loss = sum_b [ mean_i min_j d2(p1[b,i], p2[b,j]) + mean_j min_i d2(...) ]
//
// d_j = |p_j|^2 - 2 q.p_j (q^2 added after the min; -2 folded into the query).
// Packed fma.rn.f32x2 computes 2 reference points per op: 3 FFMA2 per
// (query, ref-pair). Smem holds pair-interleaved float4s so each ref-pair
// needs only 2 broadcast LDS.128 (xy pair, zw pair).
// Grid: 1024 single-warp CTAs (64 queries each) -> 6.92 avg / 7 max CTAs
// per SM = ~99% static balance across 148 SMs.

constexpr int B_      = 4;
constexpr int N_      = 8192;
constexpr int THREADS = 32;              // one warp per CTA
constexpr int QPT     = 2;               // queries per thread
constexpr int QPB     = THREADS * QPT;   // 64 queries per block
constexpr int NBLK    = N_ / QPB;        // 128 blocks per (batch, direction)
constexpr int TILE    = 1024;            // reference points cached per smem tile
constexpr int NPART   = 2 * B_ * NBLK;   // 1024 partial sums
constexpr int NBLOCKS = NPART;

__device__ float        g_partial[NPART];
__device__ unsigned int g_done = 0;

__device__ __forceinline__ uint64_t pack2(float lo, float hi) {
    uint64_t r;
    asm("mov.b64 %0, {%1, %2};" : "=l"(r) : "f"(lo), "f"(hi));
    return r;
}
__device__ __forceinline__ void unpack2(uint64_t v, float& lo, float& hi) {
    asm("mov.b64 {%0, %1}, %2;" : "=f"(lo), "=f"(hi) : "l"(v));
}
__device__ __forceinline__ uint64_t fma2(uint64_t a, uint64_t b, uint64_t c) {
    uint64_t r;
    asm("fma.rn.f32x2 %0, %1, %2, %3;" : "=l"(r) : "l"(a), "l"(b), "l"(c));
    return r;
}

__global__ __launch_bounds__(THREADS)
void chamfer_kernel(const float* __restrict__ p1, const float* __restrict__ p2,
                    float* __restrict__ out)
{
    const int blk = blockIdx.x;
    const int dir = blk >> 9;          // 0..1
    const int b   = (blk >> 7) & 3;    // 0..3
    const int qb  = blk & 127;         // 0..127

    const float* __restrict__ q = (dir == 0 ? p1 : p2) + (size_t)b * N_ * 3;
    const float* __restrict__ r = (dir == 0 ? p2 : p1) + (size_t)b * N_ * 3;

    // Pair-interleaved smem: xy[j] = {x2j, x2j+1, y2j, y2j+1},
    //                        zw[j] = {z2j, z2j+1, w2j, w2j+1}
    __shared__ float4 sh_xy[TILE / 2];
    __shared__ float4 sh_zw[TILE / 2];

    const int lane = threadIdx.x;
    const int i0   = qb * QPB + lane;
    const int i1   = i0 + THREADS;

    const float qx0 = q[i0 * 3 + 0], qy0 = q[i0 * 3 + 1], qz0 = q[i0 * 3 + 2];
    const float qx1 = q[i1 * 3 + 0], qy1 = q[i1 * 3 + 1], qz1 = q[i1 * 3 + 2];
    const float qs0 = qx0 * qx0 + qy0 * qy0 + qz0 * qz0;
    const float qs1 = qx1 * qx1 + qy1 * qy1 + qz1 * qz1;

    const uint64_t nqx0 = pack2(-2.0f * qx0, -2.0f * qx0);
    const uint64_t nqy0 = pack2(-2.0f * qy0, -2.0f * qy0);
    const uint64_t nqz0 = pack2(-2.0f * qz0, -2.0f * qz0);
    const uint64_t nqx1 = pack2(-2.0f * qx1, -2.0f * qx1);
    const uint64_t nqy1 = pack2(-2.0f * qy1, -2.0f * qy1);
    const uint64_t nqz1 = pack2(-2.0f * qz1, -2.0f * qz1);

    float m0a = 1e30f, m0b = 1e30f;
    float m1a = 1e30f, m1b = 1e30f;

    const ulonglong2* __restrict__ sxy = (const ulonglong2*)sh_xy;
    const ulonglong2* __restrict__ szw = (const ulonglong2*)sh_zw;

    for (int t = 0; t < N_; t += TILE) {
        __syncthreads();
        // Each lane stages 16 ref-pairs: points 2j, 2j+1 (6 consecutive floats,
        // 8B-aligned -> 3x LDG.64), packs xy/zw float4s, 2x STS.128.
        #pragma unroll 4
        for (int jj = lane; jj < TILE / 2; jj += THREADS) {
            const float2* rp = (const float2*)(r + (size_t)(t + 2 * jj) * 3);
            const float2 a = rp[0];   // x0 y0
            const float2 c = rp[1];   // z0 x1
            const float2 e = rp[2];   // y1 z1
            const float x0 = a.x, y0 = a.y, z0 = c.x;
            const float x1 = c.y, y1 = e.x, z1 = e.y;
            sh_xy[jj] = make_float4(x0, x1, y0, y1);
            sh_zw[jj] = make_float4(z0, z1,
                                    x0 * x0 + y0 * y0 + z0 * z0,
                                    x1 * x1 + y1 * y1 + z1 * z1);
        }
        __syncthreads();

        #pragma unroll 8
        for (int j = 0; j < TILE / 2; j++) {
            const ulonglong2 vxy = sxy[j];   // LDS.128 broadcast: px, py
            const ulonglong2 vzw = szw[j];   // LDS.128 broadcast: pz, pw
            const uint64_t px = vxy.x, py = vxy.y;
            const uint64_t pz = vzw.x, pw = vzw.y;

            uint64_t d0 = fma2(nqx0, px, pw);
            d0 = fma2(nqy0, py, d0);
            d0 = fma2(nqz0, pz, d0);
            float d0l, d0h; unpack2(d0, d0l, d0h);
            m0a = fminf(m0a, d0l);
            m0b = fminf(m0b, d0h);

            uint64_t d1 = fma2(nqx1, px, pw);
            d1 = fma2(nqy1, py, d1);
            d1 = fma2(nqz1, pz, d1);
            float d1l, d1h; unpack2(d1, d1l, d1h);
            m1a = fminf(m1a, d1l);
            m1b = fminf(m1b, d1h);
        }
    }

    // True squared distances: d = q^2 + min(|p|^2 - 2 q.p), clamped at 0
    float s = fmaxf(fminf(m0a, m0b) + qs0, 0.0f)
            + fmaxf(fminf(m1a, m1b) + qs1, 0.0f);

    // Warp reduce -> one partial per block
    #pragma unroll
    for (int o = 16; o > 0; o >>= 1)
        s += __shfl_down_sync(0xffffffffu, s, o);

    __shared__ bool amLast;
    if (lane == 0) {
        g_partial[blk] = s;
        __threadfence();
        unsigned int prev = atomicAdd(&g_done, 1u);
        amLast = (prev == NBLOCKS - 1);
    }
    __syncthreads();

    // Last finishing block: fixed-order final reduction over 1024 partials
    if (amLast) {
        float v = 0.0f;
        #pragma unroll
        for (int k = 0; k < NPART / THREADS; k++)
            v += g_partial[lane + k * THREADS];
        #pragma unroll
        for (int o = 16; o > 0; o >>= 1)
            v += __shfl_down_sync(0xffffffffu, v, o);
        if (lane == 0) {
            out[0] = v * (1.0f / (float)N_);
            g_done = 0;  // reset for next graph replay
        }
    }
}

extern "C" void kernel_launch(void* const* d_in, const int* in_sizes, int n_in,
                              void* d_out, int out_size)
{
    const float* points1 = (const float*)d_in[0];
    const float* points2 = (const float*)d_in[1];
    float* out = (float*)d_out;

    chamfer_kernel<<<NBLOCKS, THREADS>>>(points1, points2, out);
}

// round 5
// speedup vs baseline: 1.5720x; 1.1924x over previous
#include <cuda_runtime.h>
#include <cstdint>

// ChamferDistance: B=4, N=8192, C=3
// loss = sum_b [ mean_i min_j d2 + mean_j min_i d2 ]
//
// LDS broadcast costs full return bandwidth (32 lanes x data), so amortize
// each ref-pair load over QPT=8 queries per thread: per warp-iter
// LDS = 8 SM-cyc but fma = 24 FFMA2 -> fma pipe binds (~39us chip floor).
// Refs are split 16 ways across blocks for load balance; per-query partial
// mins go to a global buffer, combined by a second kernel.

constexpr int B_      = 4;
constexpr int N_      = 8192;
constexpr int THREADS = 128;            // 4 warps -> SMSPs 0..3 covered
constexpr int QPT     = 8;              // queries per thread
constexpr int QPW     = 32 * QPT;       // 256 queries per warp
constexpr int QPB     = 4 * QPW;        // 1024 queries per block
constexpr int NQG     = N_ / QPB;       // 8 query groups per (dir,b)
constexpr int NSPLIT  = 16;             // ref splits
constexpr int RPS     = N_ / NSPLIT;    // 512 refs per split
constexpr int PAIRS   = RPS / 2;        // 256 ref-pairs in smem
constexpr int NBLOCKS = 2 * B_ * NQG * NSPLIT;   // 1024
constexpr int NSLOT   = 2 * B_ * N_;    // 65536 query slots
constexpr int CBLK    = 64;             // combine-kernel blocks

__device__ float        g_qmin[NSPLIT][NSLOT];
__device__ float        g_part[CBLK];
__device__ unsigned int g_done = 0;

__device__ __forceinline__ uint64_t pack2(float lo, float hi) {
    uint64_t r;
    asm("mov.b64 %0, {%1, %2};" : "=l"(r) : "f"(lo), "f"(hi));
    return r;
}
__device__ __forceinline__ void unpack2(uint64_t v, float& lo, float& hi) {
    asm("mov.b64 {%0, %1}, %2;" : "=f"(lo), "=f"(hi) : "l"(v));
}
__device__ __forceinline__ uint64_t fma2(uint64_t a, uint64_t b, uint64_t c) {
    uint64_t r;
    asm("fma.rn.f32x2 %0, %1, %2, %3;" : "=l"(r) : "l"(a), "l"(b), "l"(c));
    return r;
}

__global__ __launch_bounds__(THREADS)
void chamfer_main(const float* __restrict__ p1, const float* __restrict__ p2)
{
    const int blk   = blockIdx.x;
    const int split = blk & (NSPLIT - 1);
    const int qg    = (blk >> 4) & (NQG - 1);
    const int b     = (blk >> 7) & 3;
    const int dir   = blk >> 9;

    const float* __restrict__ q = (dir == 0 ? p1 : p2) + (size_t)b * N_ * 3;
    const float* __restrict__ r = (dir == 0 ? p2 : p1) + (size_t)b * N_ * 3;

    // Pair-interleaved smem: xy[j]={x2j,x2j+1,y2j,y2j+1}, zw[j]={z2j,z2j+1,w2j,w2j+1}
    __shared__ float4 sh_xy[PAIRS];
    __shared__ float4 sh_zw[PAIRS];

    const int tid  = threadIdx.x;
    const int lane = tid & 31;
    const int w    = tid >> 5;

    // Stage this block's ref split (512 refs, 2 pairs per thread)
    const int rbase = split * RPS;
    #pragma unroll
    for (int jj = tid; jj < PAIRS; jj += THREADS) {
        const float2* rp = (const float2*)(r + (size_t)(rbase + 2 * jj) * 3);
        const float2 a = rp[0];   // x0 y0
        const float2 c = rp[1];   // z0 x1
        const float2 e = rp[2];   // y1 z1
        const float x0 = a.x, y0 = a.y, z0 = c.x;
        const float x1 = c.y, y1 = e.x, z1 = e.y;
        sh_xy[jj] = make_float4(x0, x1, y0, y1);
        sh_zw[jj] = make_float4(z0, z1,
                                x0 * x0 + y0 * y0 + z0 * z0,
                                x1 * x1 + y1 * y1 + z1 * z1);
    }

    // Load 8 queries per thread, pack -2q replicated
    const int qbase = qg * QPB + w * QPW + lane;
    uint64_t nqx[QPT], nqy[QPT], nqz[QPT];
    float    m[QPT];
    #pragma unroll
    for (int k = 0; k < QPT; k++) {
        const int i = qbase + k * 32;
        const float qx = q[i * 3 + 0], qy = q[i * 3 + 1], qz = q[i * 3 + 2];
        nqx[k] = pack2(-2.0f * qx, -2.0f * qx);
        nqy[k] = pack2(-2.0f * qy, -2.0f * qy);
        nqz[k] = pack2(-2.0f * qz, -2.0f * qz);
        m[k]   = 1e30f;
    }

    __syncthreads();

    const ulonglong2* __restrict__ sxy = (const ulonglong2*)sh_xy;
    const ulonglong2* __restrict__ szw = (const ulonglong2*)sh_zw;

    #pragma unroll 4
    for (int j = 0; j < PAIRS; j++) {
        const ulonglong2 vxy = sxy[j];   // LDS.128: px, py (packed pairs)
        const ulonglong2 vzw = szw[j];   // LDS.128: pz, pw
        const uint64_t px = vxy.x, py = vxy.y;
        const uint64_t pz = vzw.x, pw = vzw.y;

        #pragma unroll
        for (int k = 0; k < QPT; k++) {
            uint64_t d = fma2(nqx[k], px, pw);
            d = fma2(nqy[k], py, d);
            d = fma2(nqz[k], pz, d);
            float dl, dh; unpack2(d, dl, dh);
            m[k] = fminf(m[k], fminf(dl, dh));
        }
    }

    // Per-query partial min for this ref split (q^2 added in combine)
    const int slotbase = (dir * B_ + b) * N_ + qbase;
    #pragma unroll
    for (int k = 0; k < QPT; k++)
        g_qmin[split][slotbase + k * 32] = m[k];
}

__global__ __launch_bounds__(256)
void chamfer_combine(const float* __restrict__ p1, const float* __restrict__ p2,
                     float* __restrict__ out)
{
    const int tid = threadIdx.x;
    float s = 0.0f;

    #pragma unroll
    for (int k = 0; k < NSLOT / (CBLK * 256); k++) {
        const int slot = blockIdx.x * (NSLOT / CBLK) + k * 256 + tid;
        float mn = g_qmin[0][slot];
        #pragma unroll
        for (int sp = 1; sp < NSPLIT; sp++)
            mn = fminf(mn, g_qmin[sp][slot]);

        const int dir = slot >> 15;
        const int b   = (slot >> 13) & 3;
        const int i   = slot & (N_ - 1);
        const float* qp = (dir == 0 ? p1 : p2) + ((size_t)b * N_ + i) * 3;
        const float qx = qp[0], qy = qp[1], qz = qp[2];
        const float qs = qx * qx + qy * qy + qz * qz;
        s += fmaxf(mn + qs, 0.0f);
    }

    // Deterministic block reduce
    #pragma unroll
    for (int o = 16; o > 0; o >>= 1)
        s += __shfl_down_sync(0xffffffffu, s, o);
    __shared__ float red[8];
    __shared__ bool  amLast;
    if ((tid & 31) == 0) red[tid >> 5] = s;
    __syncthreads();
    if (tid == 0) {
        float bs = 0.0f;
        #pragma unroll
        for (int wi = 0; wi < 8; wi++) bs += red[wi];
        g_part[blockIdx.x] = bs;
        __threadfence();
        amLast = (atomicAdd(&g_done, 1u) == CBLK - 1);
    }
    __syncthreads();

    if (amLast && tid < 32) {
        float v = g_part[tid] + g_part[tid + 32];
        #pragma unroll
        for (int o = 16; o > 0; o >>= 1)
            v += __shfl_down_sync(0xffffffffu, v, o);
        if (tid == 0) {
            out[0] = v * (1.0f / (float)N_);
            g_done = 0;   // reset for next graph replay
        }
    }
}

extern "C" void kernel_launch(void* const* d_in, const int* in_sizes, int n_in,
                              void* d_out, int out_size)
{
    const float* points1 = (const float*)d_in[0];
    const float* points2 = (const float*)d_in[1];
    float* out = (float*)d_out;

    chamfer_main<<<NBLOCKS, THREADS>>>(points1, points2);
    chamfer_combine<<<CBLK, 256>>>(points1, points2, out);
}

// round 7
// speedup vs baseline: 1.7823x; 1.1338x over previous
#include <cuda_runtime.h>
#include <cstdint>

// ChamferDistance: B=4, N=8192, C=3
// loss = sum_b [ mean_i min_j d2 + mean_j min_i d2 ]
//
// d_j = |p_j|^2 - 2 q.p_j (q^2 added in combine). Inner loop per ref-pair:
// 2 LDS.128 + 3*QPT fma.rn.f32x2 + 2*QPT scalar FMNMX (unpack of the packed
// result is a register-pair alias, ~free). QPT=8 amortizes LDS broadcast cost.
// Register budget capped via __launch_bounds__(128, 4) to avoid spills.
// Refs split 16-way across blocks; per-query partial mins combined by a
// second kernel.

constexpr int B_      = 4;
constexpr int N_      = 8192;
constexpr int THREADS = 128;            // 4 warps
constexpr int QPT     = 8;              // queries per thread
constexpr int QPW     = 32 * QPT;       // 256 queries per warp
constexpr int QPB     = 4 * QPW;        // 1024 queries per block
constexpr int NQG     = N_ / QPB;       // 8 query groups per (dir,b)
constexpr int NSPLIT  = 16;             // ref splits
constexpr int RPS     = N_ / NSPLIT;    // 512 refs per split
constexpr int PAIRS   = RPS / 2;        // 256 ref-pairs in smem
constexpr int NBLOCKS = 2 * B_ * NQG * NSPLIT;   // 1024
constexpr int NSLOT   = 2 * B_ * N_;    // 65536 query slots
constexpr int CBLK    = 128;            // combine-kernel blocks

__device__ float        g_qmin[NSPLIT][NSLOT];
__device__ float        g_part[CBLK];
__device__ unsigned int g_done = 0;

__device__ __forceinline__ uint64_t pack2(float lo, float hi) {
    uint64_t r;
    asm("mov.b64 %0, {%1, %2};" : "=l"(r) : "f"(lo), "f"(hi));
    return r;
}
__device__ __forceinline__ void unpack2(uint64_t v, float& lo, float& hi) {
    asm("mov.b64 {%0, %1}, %2;" : "=f"(lo), "=f"(hi) : "l"(v));
}
__device__ __forceinline__ uint64_t fma2(uint64_t a, uint64_t b, uint64_t c) {
    uint64_t r;
    asm("fma.rn.f32x2 %0, %1, %2, %3;" : "=l"(r) : "l"(a), "l"(b), "l"(c));
    return r;
}

__global__ __launch_bounds__(THREADS, 4)
void chamfer_main(const float* __restrict__ p1, const float* __restrict__ p2)
{
    const int blk   = blockIdx.x;
    const int split = blk & (NSPLIT - 1);
    const int qg    = (blk >> 4) & (NQG - 1);
    const int b     = (blk >> 7) & 3;
    const int dir   = blk >> 9;

    const float* __restrict__ q = (dir == 0 ? p1 : p2) + (size_t)b * N_ * 3;
    const float* __restrict__ r = (dir == 0 ? p2 : p1) + (size_t)b * N_ * 3;

    // Pair-interleaved smem: xy[j]={x2j,x2j+1,y2j,y2j+1}, zw[j]={z2j,z2j+1,w2j,w2j+1}
    __shared__ float4 sh_xy[PAIRS];
    __shared__ float4 sh_zw[PAIRS];

    const int tid  = threadIdx.x;
    const int lane = tid & 31;
    const int w    = tid >> 5;

    // Stage this block's ref split (512 refs, 2 pairs per thread)
    const int rbase = split * RPS;
    #pragma unroll
    for (int jj = tid; jj < PAIRS; jj += THREADS) {
        const float2* rp = (const float2*)(r + (size_t)(rbase + 2 * jj) * 3);
        const float2 a = rp[0];   // x0 y0
        const float2 c = rp[1];   // z0 x1
        const float2 e = rp[2];   // y1 z1
        const float x0 = a.x, y0 = a.y, z0 = c.x;
        const float x1 = c.y, y1 = e.x, z1 = e.y;
        sh_xy[jj] = make_float4(x0, x1, y0, y1);
        sh_zw[jj] = make_float4(z0, z1,
                                x0 * x0 + y0 * y0 + z0 * z0,
                                x1 * x1 + y1 * y1 + z1 * z1);
    }

    // Load 8 queries per thread, pack -2q replicated
    const int qbase = qg * QPB + w * QPW + lane;
    uint64_t nqx[QPT], nqy[QPT], nqz[QPT];
    float    m[QPT];
    #pragma unroll
    for (int k = 0; k < QPT; k++) {
        const int i = qbase + k * 32;
        const float qx = q[i * 3 + 0], qy = q[i * 3 + 1], qz = q[i * 3 + 2];
        nqx[k] = pack2(-2.0f * qx, -2.0f * qx);
        nqy[k] = pack2(-2.0f * qy, -2.0f * qy);
        nqz[k] = pack2(-2.0f * qz, -2.0f * qz);
        m[k]   = 1e30f;
    }

    __syncthreads();

    const ulonglong2* __restrict__ sxy = (const ulonglong2*)sh_xy;
    const ulonglong2* __restrict__ szw = (const ulonglong2*)sh_zw;

    #pragma unroll 2
    for (int j = 0; j < PAIRS; j++) {
        const ulonglong2 vxy = sxy[j];   // LDS.128: px, py (packed ref pairs)
        const ulonglong2 vzw = szw[j];   // LDS.128: pz, pw
        const uint64_t px = vxy.x, py = vxy.y;
        const uint64_t pz = vzw.x, pw = vzw.y;

        #pragma unroll
        for (int k = 0; k < QPT; k++) {
            uint64_t d = fma2(nqx[k], px, pw);
            d = fma2(nqy[k], py, d);
            d = fma2(nqz[k], pz, d);
            float dl, dh; unpack2(d, dl, dh);   // register-pair alias
            m[k] = fminf(m[k], fminf(dl, dh));
        }
    }

    // Per-query partial min for this ref split (q^2 added in combine)
    const int slotbase = (dir * B_ + b) * N_ + qbase;
    #pragma unroll
    for (int k = 0; k < QPT; k++)
        g_qmin[split][slotbase + k * 32] = m[k];
}

__global__ __launch_bounds__(256)
void chamfer_combine(const float* __restrict__ p1, const float* __restrict__ p2,
                     float* __restrict__ out)
{
    const int tid = threadIdx.x;
    float s = 0.0f;

    #pragma unroll
    for (int k = 0; k < NSLOT / (CBLK * 256); k++) {
        const int slot = blockIdx.x * (NSLOT / CBLK) + k * 256 + tid;
        float mn = g_qmin[0][slot];
        #pragma unroll
        for (int sp = 1; sp < NSPLIT; sp++)
            mn = fminf(mn, g_qmin[sp][slot]);

        const int dir = slot >> 15;
        const int b   = (slot >> 13) & 3;
        const int i   = slot & (N_ - 1);
        const float* qp = (dir == 0 ? p1 : p2) + ((size_t)b * N_ + i) * 3;
        const float qx = qp[0], qy = qp[1], qz = qp[2];
        const float qs = qx * qx + qy * qy + qz * qz;
        s += fmaxf(mn + qs, 0.0f);
    }

    // Deterministic block reduce
    #pragma unroll
    for (int o = 16; o > 0; o >>= 1)
        s += __shfl_down_sync(0xffffffffu, s, o);
    __shared__ float red[8];
    __shared__ bool  amLast;
    if ((tid & 31) == 0) red[tid >> 5] = s;
    __syncthreads();
    if (tid == 0) {
        float bs = 0.0f;
        #pragma unroll
        for (int wi = 0; wi < 8; wi++) bs += red[wi];
        g_part[blockIdx.x] = bs;
        __threadfence();
        amLast = (atomicAdd(&g_done, 1u) == CBLK - 1);
    }
    __syncthreads();

    if (amLast && tid < 32) {
        float v = g_part[tid] + g_part[tid + 32]
                + g_part[tid + 64] + g_part[tid + 96];
        #pragma unroll
        for (int o = 16; o > 0; o >>= 1)
            v += __shfl_down_sync(0xffffffffu, v, o);
        if (tid == 0) {
            out[0] = v * (1.0f / (float)N_);
            g_done = 0;   // reset for next graph replay
        }
    }
}

extern "C" void kernel_launch(void* const* d_in, const int* in_sizes, int n_in,
                              void* d_out, int out_size)
{
    const float* points1 = (const float*)d_in[0];
    const float* points2 = (const float*)d_in[1];
    float* out = (float*)d_out;

    chamfer_main<<<NBLOCKS, THREADS>>>(points1, points2);
    chamfer_combine<<<CBLK, 256>>>(points1, points2, out);
}